// round 15
// baseline (speedup 1.0000x reference)
#include <cuda_runtime.h>
#include <cuda_bf16.h>
#include <math.h>

// ---------------- problem constants ----------------
#define BB 2
#define CM 1536
#define CS 384
#define HM 128
#define PP 1024          // 32*32 spatial
#define HI 448
#define NSEG 64
#define NSPLIT_SH 4
#define NSPLIT_G 2
#define NSPLIT_SM 4

// ---------------- scratch layout (floats) ----------------
static constexpr size_t SZ_SUMS  = (size_t)BB*NSEG*CS;
static constexpr size_t SZ_CNTS  = BB*NSEG;
static constexpr size_t SZ_RW    = 32*448;
static constexpr size_t SZ_SEMRS = (size_t)BB*CS*PP;
static constexpr size_t SZ_HSH1  = (size_t)BB*HM*PP;     // 262144
static constexpr size_t SZ_HSH3  = 3*SZ_HSH1;
static constexpr size_t SZ_G0    = (size_t)BB*CM*PP;     // 3145728
static constexpr size_t SZ_SMALL = (size_t)BB*8*PP;
static constexpr size_t SZ_MED   = (size_t)BB*16*PP;
static constexpr size_t SZ_WEFF  = 8*HM*9;

static constexpr size_t O_SUMS  = 0;
static constexpr size_t O_CNTS  = O_SUMS  + SZ_SUMS;
static constexpr size_t O_RW    = O_CNTS  + SZ_CNTS;
static constexpr size_t O_T0    = O_RW    + SZ_RW;
static constexpr size_t O_T1    = O_T0    + 32;
static constexpr size_t O_SEMRS = O_T1    + 32;
static constexpr size_t O_HSH   = O_SEMRS + SZ_SEMRS;    // final hsh (3 groups)
static constexpr size_t O_HSHS  = O_HSH   + SZ_HSH3;     // 4 split partials
static constexpr size_t O_G0S   = O_HSHS  + NSPLIT_SH*SZ_HSH3;   // 2 splits
static constexpr size_t O_LNACC = O_G0S   + NSPLIT_G*SZ_G0;
static constexpr size_t O_LNST  = O_LNACC + 4;
static constexpr size_t O_H1    = O_LNST  + 4;
static constexpr size_t O_LN1   = O_H1    + SZ_SMALL;
static constexpr size_t O_H2    = O_LN1   + 4;
static constexpr size_t O_LN2   = O_H2    + SZ_MED;
static constexpr size_t O_G1S   = O_LN2   + 4;                    // 4 x SZ_SMALL
static constexpr size_t O_BE1S  = O_G1S   + NSPLIT_SM*SZ_SMALL;
static constexpr size_t O_G2S   = O_BE1S  + NSPLIT_SM*SZ_SMALL;   // 4 x SZ_MED
static constexpr size_t O_BE2S  = O_G2S   + NSPLIT_SM*SZ_MED;
static constexpr size_t O_BCS   = O_BE2S  + NSPLIT_SM*SZ_MED;     // 4 x SZ_SMALL
// ---- zeroed-at-start region (atomic accumulators) ----
static constexpr size_t O_ZSTART= O_BCS   + NSPLIT_SM*SZ_SMALL;
static constexpr size_t O_WEFF  = O_ZSTART;
static constexpr size_t O_H1PRE = O_WEFF  + SZ_WEFF;
static constexpr size_t O_A     = O_H1PRE + SZ_SMALL;
static constexpr size_t O_BCONST= O_A     + SZ_SMALL;
static constexpr size_t O_S0    = O_BCONST+ 8;
static constexpr size_t SCRATCH_TOTAL = O_S0 + 8;
static constexpr size_t SZ_ZREG = SCRATCH_TOTAL - O_ZSTART;

__device__ float d_scratch[SCRATCH_TOTAL];

__device__ __forceinline__ float softplusf(float x) {
    return fmaxf(x, 0.f) + log1pf(expf(-fabsf(x)));
}

// ---- packed f32x2 helpers ----
__device__ __forceinline__ unsigned long long pk2(float lo, float hi) {
    unsigned long long r;
    asm("mov.b64 %0, {%1, %2};" : "=l"(r) : "f"(lo), "f"(hi));
    return r;
}
__device__ __forceinline__ void unpk2(unsigned long long v, float& lo, float& hi) {
    asm("mov.b64 {%0, %1}, %2;" : "=f"(lo), "=f"(hi) : "l"(v));
}
__device__ __forceinline__ unsigned long long ffma2(unsigned long long a, unsigned long long b,
                                                    unsigned long long c) {
    unsigned long long d;
    asm("fma.rn.f32x2 %0, %1, %2, %3;" : "=l"(d) : "l"(a), "l"(b), "l"(c));
    return d;
}

// ---------------- launch 0: zero accumulators + resize weights ----------------
__global__ void k_zero() {
    if (blockIdx.x == gridDim.x - 1) {
        int i = threadIdx.x;
        if (i >= 32) return;
        float center = (i + 0.5f) * 14.0f - 0.5f;
        float* rw = &d_scratch[O_RW + (size_t)i * 448];
        float ssum = 0.f;
        int first = -1, last = -1;
        for (int y = 0; y < 448; y++) {
            float d = fabsf(center - (float)y) * (1.0f / 14.0f);
            float w = fmaxf(0.f, 1.f - d);
            rw[y] = w;
            ssum += w;
            if (w > 0.f) { if (first < 0) first = y; last = y; }
        }
        float inv = 1.f / ssum;
        for (int y = 0; y < 448; y++) rw[y] *= inv;
        ((int*)&d_scratch[O_T0])[i] = first;
        ((int*)&d_scratch[O_T1])[i] = last;
        return;
    }
    size_t idx = (size_t)blockIdx.x * blockDim.x + threadIdx.x;
    size_t stride = (size_t)(gridDim.x - 1) * blockDim.x;
    for (size_t i = idx; i < SZ_ZREG; i += stride) d_scratch[O_ZSTART + i] = 0.f;
    if (idx < 4) d_scratch[O_LNACC + idx] = 0.f;
}

// ---------------- launch 1: segment sums (coalesced, smem histogram) ------------
__global__ void __launch_bounds__(256) k_seg_acc(const float* __restrict__ fsem,
                                                 const int* __restrict__ seg) {
    __shared__ float hist[NSEG * 8];
    __shared__ int sid[PP];
    __shared__ int cnt[NSEG];
    int bc = blockIdx.x;
    int b = bc / 48;
    int cch = bc - b * 48;
    int tid = threadIdx.x;
    for (int t = tid; t < NSEG * 8; t += 256) hist[t] = 0.f;
    if (tid < NSEG) cnt[tid] = 0;
    for (int p = tid; p < PP; p += 256) {
        int i = p >> 5, j = p & 31;
        int s = seg[(size_t)b * (HI*HI) + (size_t)(i * 14) * HI + (j * 14)];
        sid[p] = min(max(s, 0), NSEG - 1);
    }
    __syncthreads();
    #pragma unroll
    for (int cl = 0; cl < 8; cl++) {
        const float* f = fsem + ((size_t)b * CS + cch * 8 + cl) * PP;
        for (int p = tid; p < PP; p += 256)
            atomicAdd(&hist[sid[p] * 8 + cl], f[p]);
    }
    if (cch == 0)
        for (int p = tid; p < PP; p += 256) atomicAdd(&cnt[sid[p]], 1);
    __syncthreads();
    for (int t = tid; t < NSEG * 8; t += 256) {
        int s = t >> 3, cl = t & 7;
        d_scratch[O_SUMS + ((size_t)(b * NSEG + s)) * CS + cch * 8 + cl] = hist[t];
    }
    if (cch == 0 && tid < NSEG)
        d_scratch[O_CNTS + b * NSEG + tid] = (float)cnt[tid];
}

// ---------------- launch 2: fused wseg histogram + avg-fold + sem_rs GEMM --------
__global__ void __launch_bounds__(256) k_semrs_fused(const int* __restrict__ seg) {
    __shared__ float hist[32 * 261];
    __shared__ float avgsh[64 * 52];
    __shared__ float csh[64];
    int tid = threadIdx.x;
    int i = blockIdx.x;
    int b = blockIdx.y;

    for (int t = tid; t < 32 * 261; t += 256) hist[t] = 0.f;
    __syncthreads();

    const float* sums = &d_scratch[O_SUMS + (size_t)b * NSEG * CS];
    if (tid < 128) {
        int j = tid >> 2, lane = tid & 3;
        const int* t0 = (const int*)&d_scratch[O_T0];
        const int* t1 = (const int*)&d_scratch[O_T1];
        int ya = t0[i], yb = t1[i], xa = t0[j], xb = t1[j];
        const float* rwi = &d_scratch[O_RW + (size_t)i * 448];
        const float* rwj = &d_scratch[O_RW + (size_t)j * 448];
        const int* segb = seg + (size_t)b * (HI*HI);
        float* my = &hist[j * 261 + lane * 65];
        for (int y = ya + lane; y <= yb; y += 4) {
            float ry = rwi[y];
            const int* srow = segb + (size_t)y * HI;
            for (int x = xa; x <= xb; x++) {
                float wv = ry * rwj[x];
                int s = srow[x];
                s = min(max(s, 0), NSEG - 1);
                my[s] += wv;
            }
        }
    } else {
        int t2 = tid - 128;
        if (t2 < 64) {
            float cw = d_scratch[O_CNTS + b * NSEG + t2];
            csh[t2] = (cw > 0.f) ? 1.f / cw : 0.f;
        }
        for (int t = t2; t < 64 * 48; t += 128) {
            int s = t / 48, c = t - s * 48;
            avgsh[s * 52 + c] = sums[(size_t)s * CS + c];
        }
    }
    __syncthreads();

    {
        int j = tid >> 3, sg = tid & 7;
        #pragma unroll
        for (int k = 0; k < 8; k++) {
            int s = sg * 8 + k;
            float w = hist[j * 261 + s] + hist[j * 261 + 65 + s]
                    + hist[j * 261 + 130 + s] + hist[j * 261 + 195 + s];
            hist[j * 261 + s] = w * csh[s];
        }
    }
    __syncthreads();

    int j = tid & 31;
    int csub = tid >> 5;
    const float* Wrow = &hist[j * 261];
    float* sem = &d_scratch[O_SEMRS + (size_t)b * CS * PP];
    for (int ch = 0; ch < 8; ch++) {
        if (ch > 0) {
            __syncthreads();
            for (int t = tid; t < 64 * 48; t += 256) {
                int s = t / 48, c = t - s * 48;
                avgsh[s * 52 + c] = sums[(size_t)s * CS + ch * 48 + c];
            }
            __syncthreads();
        }
        float acc[6] = {0.f, 0.f, 0.f, 0.f, 0.f, 0.f};
        for (int s = 0; s < 64; s++) {
            float w = Wrow[s];
            const float* av = &avgsh[s * 52 + csub * 6];
            #pragma unroll
            for (int k = 0; k < 6; k++) acc[k] += w * av[k];
        }
        int cbase = ch * 48 + csub * 6;
        #pragma unroll
        for (int k = 0; k < 6; k++)
            sem[(size_t)(cbase + k) * PP + i * 32 + j] = acc[k];
    }
}

// ---------------- 3x3 conv v3: f32x2 packed FMA, float4 staging, CIN-split -------
// Weights staged as duplicated (w,w) u64 -> LDS.64 broadcast. Window loaded scalar
// (SMW=35 conflict-free), packed into even/odd f32x2 pairs amortized over TH_CO.
template<int CIN_TOT, int CIN_SUB, int COUT_PER, int CO_T, int TH_CO, int MINB>
__global__ void __launch_bounds__((CO_T / TH_CO) * 32, MINB)
conv3x3_v2(const float* __restrict__ in,
           const float* __restrict__ w0, const float* __restrict__ w1, const float* __restrict__ w2,
           float* __restrict__ o0, float* __restrict__ o1, float* __restrict__ o2,
           size_t split_stride)
{
    constexpr int CK = 4;
    constexpr int ROWS = 8;
    constexpr int NT = (CO_T / TH_CO) * 32;
    constexpr int SMW = 35;
    constexpr int PLANE = (ROWS + 2) * SMW;
    constexpr int NCH = CIN_SUB / CK;
    __shared__ float sIn[2][CK * PLANE];
    __shared__ unsigned long long sW[2][CK * CO_T * 9];

    const int tid = threadIdx.x;
    const int b = blockIdx.z;
    const int yb = blockIdx.y;
    const int split = yb >> 2;
    const int r0 = (yb & 3) * ROWS;
    const int co_glob = blockIdx.x * CO_T;
    const int grp = co_glob / COUT_PER;
    const int co0 = co_glob % COUT_PER;
    const float* w = (grp == 0) ? w0 : ((grp == 1) ? w1 : w2);
    float* out = ((grp == 0) ? o0 : ((grp == 1) ? o1 : o2)) + (size_t)split * split_stride;

    const int pg = tid & 31;
    const int cg = tid >> 5;
    const int lr = (pg * 8) >> 5;
    const int col0 = (pg * 8) & 31;
    const int gy = r0 + lr;

    const float* inb = in + ((size_t)b * CIN_TOT + (size_t)split * CIN_SUB) * PP;

    unsigned long long acc2[TH_CO * 4];
    #pragma unroll
    for (int t = 0; t < TH_CO * 4; t++) acc2[t] = 0ull;

    // one-time zero of both input buffers (halo + invalid rows stay zero forever)
    for (int t = tid; t < 2 * CK * PLANE; t += NT) (&sIn[0][0])[t] = 0.f;

    auto stage = [&](int c0, int buf) {
        float* dIn = sIn[buf];
        unsigned long long* dW = sW[buf];
        // body: CK channels x 10 rows x 8 float4
        for (int idx = tid; idx < CK * 80; idx += NT) {
            int k = idx / 80;
            int rem = idx - k * 80;
            int r = rem >> 3;
            int v = rem & 7;
            int iy = r0 - 1 + r;
            if (iy >= 0 && iy < 32) {
                float4 val = *(const float4*)&inb[(size_t)(c0 + k) * PP + iy * 32 + v * 4];
                float* d = &dIn[k * PLANE + r * SMW + 1 + v * 4];
                d[0] = val.x; d[1] = val.y; d[2] = val.z; d[3] = val.w;
            }
        }
        for (int idx = tid; idx < CK * CO_T * 9; idx += NT) {
            int k = idx / (CO_T * 9);
            int rem = idx - k * (CO_T * 9);
            int co = rem / 9;
            int t = rem - co * 9;
            float wv = w[((size_t)(co0 + co) * CIN_TOT + split * CIN_SUB + c0 + k) * 9 + t];
            unsigned int u = __float_as_uint(wv);
            dW[idx] = ((unsigned long long)u << 32) | (unsigned long long)u;
        }
    };

    __syncthreads();
    stage(0, 0);
    __syncthreads();
    for (int cc = 0; cc < NCH; cc++) {
        int buf = cc & 1;
        if (cc + 1 < NCH) stage((cc + 1) * CK, buf ^ 1);
        #pragma unroll
        for (int k = 0; k < CK; k++) {
            const float* pl = &sIn[buf][k * PLANE + lr * SMW + col0];
            const unsigned long long* wk = &sW[buf][k * CO_T * 9 + cg * TH_CO * 9];
            #pragma unroll
            for (int ky = 0; ky < 3; ky++) {
                float win[10];
                #pragma unroll
                for (int t = 0; t < 10; t++) win[t] = pl[ky * SMW + t];
                // even pairs A[j]=(win[2j],win[2j+1]) j=0..4, odd pairs O[j]=(win[2j+1],win[2j+2]) j=0..3
                unsigned long long A[5], O[4];
                #pragma unroll
                for (int t = 0; t < 5; t++) A[t] = pk2(win[2 * t], win[2 * t + 1]);
                #pragma unroll
                for (int t = 0; t < 4; t++) O[t] = pk2(win[2 * t + 1], win[2 * t + 2]);
                #pragma unroll
                for (int co = 0; co < TH_CO; co++) {
                    unsigned long long wa = wk[co * 9 + ky * 3 + 0];
                    unsigned long long wb = wk[co * 9 + ky * 3 + 1];
                    unsigned long long wc = wk[co * 9 + ky * 3 + 2];
                    #pragma unroll
                    for (int j = 0; j < 4; j++) {
                        unsigned long long a = acc2[co * 4 + j];
                        a = ffma2(A[j],     wa, a);
                        a = ffma2(O[j],     wb, a);
                        a = ffma2(A[j + 1], wc, a);
                        acc2[co * 4 + j] = a;
                    }
                }
            }
        }
        __syncthreads();
    }
    #pragma unroll
    for (int co = 0; co < TH_CO; co++) {
        int oc = co0 + cg * TH_CO + co;
        float2* op = (float2*)&out[((size_t)b * COUT_PER + oc) * PP + gy * 32 + col0];
        #pragma unroll
        for (int j = 0; j < 4; j++) {
            float v0, v1;
            unpk2(acc2[co * 4 + j], v0, v1);
            op[j] = make_float2(v0, v1);
        }
    }
}

// ---------------- hsh epilogue: relu(sum of 4 splits + bias) ----------------
__global__ void k_hsh_epi(const float* __restrict__ b0, const float* __restrict__ b1,
                          const float* __restrict__ b2) {
    int idx = blockIdx.x * 256 + threadIdx.x;
    if (idx >= (int)SZ_HSH3) return;
    int g = idx / (int)SZ_HSH1;
    int ch = (idx >> 10) % HM;
    const float* bp = (g == 0) ? b0 : ((g == 1) ? b1 : b2);
    float v = d_scratch[O_HSHS + idx] + d_scratch[O_HSHS + SZ_HSH3 + idx]
            + d_scratch[O_HSHS + 2*SZ_HSH3 + idx] + d_scratch[O_HSHS + 3*SZ_HSH3 + idx]
            + bp[ch];
    d_scratch[O_HSH + idx] = fmaxf(v, 0.f);
}

// ---------------- layernorm stats ----------------
__global__ void k_ln_big(const float* __restrict__ x) {
    int b = blockIdx.y;
    const float* xb = x + (size_t)b * CM * PP;
    const int chunk = CM * PP / 64;
    int start = blockIdx.x * chunk;
    float s = 0.f, q = 0.f;
    #pragma unroll 4
    for (int i = threadIdx.x; i < chunk; i += 256) {
        float v = xb[start + i];
        s += v; q += v * v;
    }
    __shared__ float ss[256], sq[256];
    int t = threadIdx.x;
    ss[t] = s; sq[t] = q;
    __syncthreads();
    for (int o = 128; o > 0; o >>= 1) {
        if (t < o) { ss[t] += ss[t + o]; sq[t] += sq[t + o]; }
        __syncthreads();
    }
    if (t == 0) {
        atomicAdd(&d_scratch[O_LNACC + b * 2 + 0], ss[0]);
        atomicAdd(&d_scratch[O_LNACC + b * 2 + 1], sq[0]);
    }
}

__global__ void k_ln_fin() {
    int b = threadIdx.x;
    if (b >= BB) return;
    float N = (float)(CM * PP);
    float mu = d_scratch[O_LNACC + b * 2] / N;
    float var = d_scratch[O_LNACC + b * 2 + 1] / N - mu * mu;
    d_scratch[O_LNST + b * 2] = mu;
    d_scratch[O_LNST + b * 2 + 1] = rsqrtf(fmaxf(var, 0.f) + 1e-12f);
}

__global__ void k_ln_small(size_t off_in, int n, size_t off_stat) {
    int b = blockIdx.x;
    const float* p = &d_scratch[off_in + (size_t)b * n];
    float s = 0.f, q = 0.f;
    for (int i = threadIdx.x; i < n; i += 256) {
        float v = p[i]; s += v; q += v * v;
    }
    __shared__ float ss[256], sq[256];
    int t = threadIdx.x;
    ss[t] = s; sq[t] = q;
    __syncthreads();
    for (int o = 128; o > 0; o >>= 1) {
        if (t < o) { ss[t] += ss[t + o]; sq[t] += sq[t + o]; }
        __syncthreads();
    }
    if (t == 0) {
        float N = (float)n;
        float mu = ss[0] / N;
        float var = sq[0] / N - mu * mu;
        d_scratch[off_stat + b * 2] = mu;
        d_scratch[off_stat + b * 2 + 1] = rsqrtf(fmaxf(var, 0.f) + 1e-12f);
    }
}

// ---------------- pre-contract w_be0 with wc0 ----------------
__global__ void k_weff(const float* __restrict__ w_be0, const float* __restrict__ b_be0,
                       const float* __restrict__ wc0) {
    __shared__ float sw[8 * 384];
    int tid = threadIdx.x;
    int mtb = blockIdx.x;
    int cch = blockIdx.y;
    int c0 = cch * 384;
    for (int idx = tid; idx < 8 * 384; idx += 128) {
        int o = idx / 384;
        int cl = idx - o * 384;
        sw[idx] = wc0[(size_t)o * CM + c0 + cl];
    }
    __syncthreads();
    int mt = mtb * 128 + tid;
    float acc[8];
    #pragma unroll
    for (int o = 0; o < 8; o++) acc[o] = 0.f;
    for (int cl = 0; cl < 384; cl++) {
        float wv = w_be0[(size_t)(c0 + cl) * (HM * 9) + mt];
        #pragma unroll
        for (int o = 0; o < 8; o++) acc[o] += sw[o * 384 + cl] * wv;
    }
    #pragma unroll
    for (int o = 0; o < 8; o++)
        atomicAdd(&d_scratch[O_WEFF + (size_t)o * (HM * 9) + mt], acc[o]);
    if (mtb == 0 && tid < 8) {
        int o = tid;
        float bc = 0.f, s0 = 0.f;
        for (int cl = 0; cl < 384; cl++) {
            float wcv = sw[o * 384 + cl];
            bc += wcv * b_be0[c0 + cl];
            s0 += wcv;
        }
        atomicAdd(&d_scratch[O_BCONST + o], bc);
        atomicAdd(&d_scratch[O_S0 + o], s0);
    }
}

// ---------------- combine0: G = wc0.(xn*gamma), A = wc0.x ----------------
__global__ void k_combine0(const float* __restrict__ x, const float* __restrict__ wc0,
                           const float* __restrict__ bg0) {
    __shared__ float sw[8 * 24];
    __shared__ float sb[24];
    int tid = threadIdx.x;
    int b = blockIdx.z;
    int cc = blockIdx.y;               // 0..63, 24 channels each
    int p = blockIdx.x * 256 + tid;
    if (tid < 8 * 24) {
        int o = tid / 24;
        int c = tid - o * 24;
        sw[tid] = wc0[(size_t)o * CM + cc * 24 + c];
    }
    if (tid >= 224 && tid < 248) sb[tid - 224] = bg0[cc * 24 + (tid - 224)];
    __syncthreads();
    float mu = d_scratch[O_LNST + b * 2];
    float rs = d_scratch[O_LNST + b * 2 + 1];
    float accG[8], accA[8];
    #pragma unroll
    for (int o = 0; o < 8; o++) { accG[o] = 0.f; accA[o] = 0.f; }
    size_t base = ((size_t)b * CM + (size_t)cc * 24) * PP + p;
    const float* g0 = &d_scratch[O_G0S];
    #pragma unroll 4
    for (int c = 0; c < 24; c++) {
        size_t a = base + (size_t)c * PP;
        float xv = x[a];
        float gv = g0[a] + g0[a + SZ_G0] + sb[c];
        float val = (xv - mu) * rs * gv;
        #pragma unroll
        for (int o = 0; o < 8; o++) {
            float wv = sw[o * 24 + c];
            accG[o] += wv * val;
            accA[o] += wv * xv;
        }
    }
    #pragma unroll
    for (int o = 0; o < 8; o++) {
        atomicAdd(&d_scratch[O_H1PRE + ((size_t)b * 8 + o) * PP + p], accG[o]);
        atomicAdd(&d_scratch[O_A     + ((size_t)b * 8 + o) * PP + p], accA[o]);
    }
}

// ---------------- assemble h1 (sums 4 beta-conv splits) ----------------
__global__ void k_bias_sp0(const float* __restrict__ bias0) {
    int idx = blockIdx.x * blockDim.x + threadIdx.x;
    if (idx >= (int)SZ_SMALL) return;
    int b = idx >> 13;
    int o = (idx >> 10) & 7;
    float mu = d_scratch[O_LNST + b * 2];
    float rs = d_scratch[O_LNST + b * 2 + 1];
    float bc = d_scratch[O_BCS + idx] + d_scratch[O_BCS + SZ_SMALL + idx]
             + d_scratch[O_BCS + 2*SZ_SMALL + idx] + d_scratch[O_BCS + 3*SZ_SMALL + idx];
    float v = d_scratch[O_H1PRE + idx]
            + (d_scratch[O_A + idx] - mu * d_scratch[O_S0 + o]) * rs
            + bc
            + d_scratch[O_BCONST + o]
            + bias0[o];
    d_scratch[O_H1 + idx] = softplusf(v);
}

// ---------------- spade1 combine + 1x1 (8->16) + softplus ----------------
__global__ void __launch_bounds__(128) k_combine1(const float* __restrict__ wc1,
                           const float* __restrict__ bias1,
                           const float* __restrict__ bg1, const float* __restrict__ bbe1) {
    int b = blockIdx.y;
    int p = blockIdx.x * 128 + threadIdx.x;
    float mu = d_scratch[O_LN1 + b * 2];
    float rs = d_scratch[O_LN1 + b * 2 + 1];
    float val[8];
    #pragma unroll
    for (int c = 0; c < 8; c++) {
        size_t a = ((size_t)b * 8 + c) * PP + p;
        float hv = d_scratch[O_H1 + a];
        float gv = d_scratch[O_G1S + a] + d_scratch[O_G1S + SZ_SMALL + a]
                 + d_scratch[O_G1S + 2*SZ_SMALL + a] + d_scratch[O_G1S + 3*SZ_SMALL + a]
                 + bg1[c];
        float bv = d_scratch[O_BE1S + a] + d_scratch[O_BE1S + SZ_SMALL + a]
                 + d_scratch[O_BE1S + 2*SZ_SMALL + a] + d_scratch[O_BE1S + 3*SZ_SMALL + a]
                 + bbe1[c];
        val[c] = (hv - mu) * rs * (1.f + gv) + bv;
    }
    #pragma unroll
    for (int o = 0; o < 16; o++) {
        float a = bias1[o];
        #pragma unroll
        for (int c = 0; c < 8; c++) a += wc1[o * 8 + c] * val[c];
        d_scratch[O_H2 + ((size_t)b * 16 + o) * PP + p] = softplusf(a);
    }
}

// ---------------- spade2 combine + 1x1 (16->1) + softplus -> output ------------
__global__ void __launch_bounds__(128) k_combine2(const float* __restrict__ wc2,
                           const float* __restrict__ bias2,
                           const float* __restrict__ bg2, const float* __restrict__ bbe2,
                           float* __restrict__ out) {
    int b = blockIdx.y;
    int p = blockIdx.x * 128 + threadIdx.x;
    float mu = d_scratch[O_LN2 + b * 2];
    float rs = d_scratch[O_LN2 + b * 2 + 1];
    float a = bias2[0];
    #pragma unroll
    for (int c = 0; c < 16; c++) {
        size_t idx = ((size_t)b * 16 + c) * PP + p;
        float hv = d_scratch[O_H2 + idx];
        float gv = d_scratch[O_G2S + idx] + d_scratch[O_G2S + SZ_MED + idx]
                 + d_scratch[O_G2S + 2*SZ_MED + idx] + d_scratch[O_G2S + 3*SZ_MED + idx]
                 + bg2[c];
        float bv = d_scratch[O_BE2S + idx] + d_scratch[O_BE2S + SZ_MED + idx]
                 + d_scratch[O_BE2S + 2*SZ_MED + idx] + d_scratch[O_BE2S + 3*SZ_MED + idx]
                 + bbe2[c];
        float val = (hv - mu) * rs * (1.f + gv) + bv;
        a += wc2[c] * val;
    }
    out[(size_t)b * PP + p] = softplusf(a);
}

// ---------------- launch ----------------
extern "C" void kernel_launch(void* const* d_in, const int* in_sizes, int n_in,
                              void* d_out, int out_size) {
    const float* x_main = (const float*)d_in[0];
    const float* f_sem  = (const float*)d_in[1];
    const float* w_sh0  = (const float*)d_in[2];
    const float* b_sh0  = (const float*)d_in[3];
    const float* w_g0   = (const float*)d_in[4];
    const float* b_g0   = (const float*)d_in[5];
    const float* w_be0  = (const float*)d_in[6];
    const float* b_be0  = (const float*)d_in[7];
    const float* w_sh1  = (const float*)d_in[8];
    const float* b_sh1  = (const float*)d_in[9];
    const float* w_g1   = (const float*)d_in[10];
    const float* b_g1   = (const float*)d_in[11];
    const float* w_be1  = (const float*)d_in[12];
    const float* b_be1  = (const float*)d_in[13];
    const float* w_sh2  = (const float*)d_in[14];
    const float* b_sh2  = (const float*)d_in[15];
    const float* w_g2   = (const float*)d_in[16];
    const float* b_g2   = (const float*)d_in[17];
    const float* w_be2  = (const float*)d_in[18];
    const float* b_be2  = (const float*)d_in[19];
    const float* w_c0   = (const float*)d_in[20];
    const float* bias0  = (const float*)d_in[21];
    const float* w_c1   = (const float*)d_in[22];
    const float* bias1  = (const float*)d_in[23];
    const float* w_c2   = (const float*)d_in[24];
    const float* bias2  = (const float*)d_in[25];
    const int*   segmap = (const int*)d_in[26];

    float* S = nullptr;
    cudaGetSymbolAddress((void**)&S, d_scratch);
    float* semrs = S + O_SEMRS;
    float* hsh0 = S + O_HSH;
    float* hsh1 = S + O_HSH + SZ_HSH1;
    float* hsh2 = S + O_HSH + 2 * SZ_HSH1;
    float* hshS0 = S + O_HSHS;
    float* hshS1 = S + O_HSHS + SZ_HSH1;
    float* hshS2 = S + O_HSHS + 2 * SZ_HSH1;
    float* g0s = S + O_G0S;
    float* g1s  = S + O_G1S;
    float* be1s = S + O_BE1S;
    float* g2s  = S + O_G2S;
    float* be2s = S + O_BE2S;
    float* bcs  = S + O_BCS;
    float* weff = S + O_WEFF;

    // 0
    k_zero<<<129, 256>>>();
    // 1: coalesced segment sums
    k_seg_acc<<<BB * 48, 256>>>(f_sem, segmap);
    // 2: fused wseg + avg-fold + sem_rs
    k_semrs_fused<<<dim3(32, BB), 256>>>(segmap);
    // 3: shared convs (3 groups, CIN split 4, f32x2)  << ncu slot >>
    conv3x3_v2<CS, CS/NSPLIT_SH, HM, 16, 4, 5><<<dim3(3 * HM / 16, 4 * NSPLIT_SH, BB), 128>>>(
        semrs, w_sh0, w_sh1, w_sh2, hshS0, hshS1, hshS2, SZ_HSH3);
    // 4: epilogue -> hsh
    k_hsh_epi<<<(int)(SZ_HSH3 / 256), 256>>>(b_sh0, b_sh1, b_sh2);
    // 5: gamma conv: 128->1536, split 2, f32x2
    conv3x3_v2<HM, HM/NSPLIT_G, CM, 16, 4, 5><<<dim3(CM / 16, 4 * NSPLIT_G, BB), 128>>>(
        hsh0, w_g0, w_g0, w_g0, g0s, g0s, g0s, SZ_G0);
    // 6,7
    k_ln_big<<<dim3(64, BB), 256>>>(x_main);
    k_ln_fin<<<1, 32>>>();
    // 8: beta-path weight pre-contraction
    k_weff<<<dim3(9, 4), 128>>>(w_be0, b_be0, w_c0);
    // 9: beta-path conv 128 -> 8, split 4
    conv3x3_v2<HM, HM/NSPLIT_SM, 8, 8, 2, 8><<<dim3(1, 4 * NSPLIT_SM, BB), 128>>>(
        hsh0, weff, weff, weff, bcs, bcs, bcs, SZ_SMALL);
    // 10: combine0 (G and A partial sums), 512 blocks
    k_combine0<<<dim3(4, 64, BB), 256>>>(x_main, w_c0, b_g0);
    // 11
    k_bias_sp0<<<(int)(SZ_SMALL / 256), 256>>>(bias0);
    // 12
    k_ln_small<<<BB, 256>>>(O_H1, 8 * PP, O_LN1);
    // 13: spade1 gamma+beta convs: 128 -> 8 (x2 groups), split 4
    conv3x3_v2<HM, HM/NSPLIT_SM, 8, 8, 2, 8><<<dim3(2, 4 * NSPLIT_SM, BB), 128>>>(
        hsh1, w_g1, w_be1, w_be1, g1s, be1s, be1s, SZ_SMALL);
    // 14
    k_combine1<<<dim3(8, BB), 128>>>(w_c1, bias1, b_g1, b_be1);
    // 15
    k_ln_small<<<BB, 256>>>(O_H2, 16 * PP, O_LN2);
    // 16: spade2 gamma+beta convs: 128 -> 16 (x2 groups), split 4
    conv3x3_v2<HM, HM/NSPLIT_SM, 16, 8, 2, 8><<<dim3(4, 4 * NSPLIT_SM, BB), 128>>>(
        hsh2, w_g2, w_be2, w_be2, g2s, be2s, be2s, SZ_MED);
    // 17
    k_combine2<<<dim3(8, BB), 128>>>(w_c2, bias2, b_g2, b_be2, (float*)d_out);
}

// round 16
// speedup vs baseline: 1.8485x; 1.8485x over previous
#include <cuda_runtime.h>
#include <cuda_bf16.h>
#include <math.h>

// ---------------- problem constants ----------------
#define BB 2
#define CM 1536
#define CS 384
#define HM 128
#define PP 1024          // 32*32 spatial
#define HI 448
#define NSEG 64
#define NSPLIT_SH 2
#define NSPLIT_SM 4

// ---------------- scratch layout (floats) ----------------
static constexpr size_t SZ_SUMS  = (size_t)BB*NSEG*CS;
static constexpr size_t SZ_CNTS  = BB*NSEG;
static constexpr size_t SZ_RW    = 32*448;
static constexpr size_t SZ_SEMRS = (size_t)BB*CS*PP;
static constexpr size_t SZ_HSH1  = (size_t)BB*HM*PP;     // 262144
static constexpr size_t SZ_HSH3  = 3*SZ_HSH1;
static constexpr size_t SZ_G0    = (size_t)BB*CM*PP;     // 3145728
static constexpr size_t SZ_SMALL = (size_t)BB*8*PP;
static constexpr size_t SZ_MED   = (size_t)BB*16*PP;
static constexpr size_t SZ_WEFF  = 8*HM*9;

static constexpr size_t O_SUMS  = 0;
static constexpr size_t O_CNTS  = O_SUMS  + SZ_SUMS;
static constexpr size_t O_RW    = O_CNTS  + SZ_CNTS;
static constexpr size_t O_T0    = O_RW    + SZ_RW;
static constexpr size_t O_T1    = O_T0    + 32;
static constexpr size_t O_SEMRS = O_T1    + 32;
static constexpr size_t O_HSH   = O_SEMRS + SZ_SEMRS;    // final hsh (3 groups)
static constexpr size_t O_HSHS  = O_HSH   + SZ_HSH3;     // 2 split partials
static constexpr size_t O_G0S   = O_HSHS  + NSPLIT_SH*SZ_HSH3;   // 1 buffer
static constexpr size_t O_LNACC = O_G0S   + SZ_G0;
static constexpr size_t O_LNST  = O_LNACC + 4;
static constexpr size_t O_H1    = O_LNST  + 4;
static constexpr size_t O_LN1   = O_H1    + SZ_SMALL;
static constexpr size_t O_H2    = O_LN1   + 4;
static constexpr size_t O_LN2   = O_H2    + SZ_MED;
static constexpr size_t O_G1S   = O_LN2   + 4;                    // 4 x SZ_SMALL
static constexpr size_t O_BE1S  = O_G1S   + NSPLIT_SM*SZ_SMALL;
static constexpr size_t O_G2S   = O_BE1S  + NSPLIT_SM*SZ_SMALL;   // 4 x SZ_MED
static constexpr size_t O_BE2S  = O_G2S   + NSPLIT_SM*SZ_MED;
static constexpr size_t O_BCS   = O_BE2S  + NSPLIT_SM*SZ_MED;     // 4 x SZ_SMALL
// ---- zeroed-at-start region (atomic accumulators) ----
static constexpr size_t O_ZSTART= O_BCS   + NSPLIT_SM*SZ_SMALL;
static constexpr size_t O_WEFF  = O_ZSTART;
static constexpr size_t O_H1PRE = O_WEFF  + SZ_WEFF;
static constexpr size_t O_A     = O_H1PRE + SZ_SMALL;
static constexpr size_t O_BCONST= O_A     + SZ_SMALL;
static constexpr size_t O_S0    = O_BCONST+ 8;
static constexpr size_t SCRATCH_TOTAL = O_S0 + 8;
static constexpr size_t SZ_ZREG = SCRATCH_TOTAL - O_ZSTART;

__device__ float d_scratch[SCRATCH_TOTAL];

__device__ __forceinline__ float softplusf(float x) {
    return fmaxf(x, 0.f) + log1pf(expf(-fabsf(x)));
}

__device__ __forceinline__ unsigned int to_tf32(float f) {
    unsigned int r;
    asm("cvt.rna.tf32.f32 %0, %1;" : "=r"(r) : "f"(f));
    return r;
}

// ---------------- launch 0: zero accumulators + resize weights ----------------
__global__ void k_zero() {
    if (blockIdx.x == gridDim.x - 1) {
        int i = threadIdx.x;
        if (i >= 32) return;
        float center = (i + 0.5f) * 14.0f - 0.5f;
        float* rw = &d_scratch[O_RW + (size_t)i * 448];
        float ssum = 0.f;
        int first = -1, last = -1;
        for (int y = 0; y < 448; y++) {
            float d = fabsf(center - (float)y) * (1.0f / 14.0f);
            float w = fmaxf(0.f, 1.f - d);
            rw[y] = w;
            ssum += w;
            if (w > 0.f) { if (first < 0) first = y; last = y; }
        }
        float inv = 1.f / ssum;
        for (int y = 0; y < 448; y++) rw[y] *= inv;
        ((int*)&d_scratch[O_T0])[i] = first;
        ((int*)&d_scratch[O_T1])[i] = last;
        return;
    }
    size_t idx = (size_t)blockIdx.x * blockDim.x + threadIdx.x;
    size_t stride = (size_t)(gridDim.x - 1) * blockDim.x;
    for (size_t i = idx; i < SZ_ZREG; i += stride) d_scratch[O_ZSTART + i] = 0.f;
    if (idx < 4) d_scratch[O_LNACC + idx] = 0.f;
}

// ---------------- launch 1: segment sums (coalesced, smem histogram) ------------
__global__ void __launch_bounds__(256) k_seg_acc(const float* __restrict__ fsem,
                                                 const int* __restrict__ seg) {
    __shared__ float hist[NSEG * 8];
    __shared__ int sid[PP];
    __shared__ int cnt[NSEG];
    int bc = blockIdx.x;
    int b = bc / 48;
    int cch = bc - b * 48;
    int tid = threadIdx.x;
    for (int t = tid; t < NSEG * 8; t += 256) hist[t] = 0.f;
    if (tid < NSEG) cnt[tid] = 0;
    for (int p = tid; p < PP; p += 256) {
        int i = p >> 5, j = p & 31;
        int s = seg[(size_t)b * (HI*HI) + (size_t)(i * 14) * HI + (j * 14)];
        sid[p] = min(max(s, 0), NSEG - 1);
    }
    __syncthreads();
    #pragma unroll
    for (int cl = 0; cl < 8; cl++) {
        const float* f = fsem + ((size_t)b * CS + cch * 8 + cl) * PP;
        for (int p = tid; p < PP; p += 256)
            atomicAdd(&hist[sid[p] * 8 + cl], f[p]);
    }
    if (cch == 0)
        for (int p = tid; p < PP; p += 256) atomicAdd(&cnt[sid[p]], 1);
    __syncthreads();
    for (int t = tid; t < NSEG * 8; t += 256) {
        int s = t >> 3, cl = t & 7;
        d_scratch[O_SUMS + ((size_t)(b * NSEG + s)) * CS + cch * 8 + cl] = hist[t];
    }
    if (cch == 0 && tid < NSEG)
        d_scratch[O_CNTS + b * NSEG + tid] = (float)cnt[tid];
}

// ---------------- launch 2: fused wseg histogram + avg-fold + sem_rs GEMM --------
__global__ void __launch_bounds__(256) k_semrs_fused(const int* __restrict__ seg) {
    __shared__ float hist[32 * 261];
    __shared__ float avgsh[64 * 52];
    __shared__ float csh[64];
    int tid = threadIdx.x;
    int i = blockIdx.x;
    int b = blockIdx.y;

    for (int t = tid; t < 32 * 261; t += 256) hist[t] = 0.f;
    __syncthreads();

    const float* sums = &d_scratch[O_SUMS + (size_t)b * NSEG * CS];
    if (tid < 128) {
        int j = tid >> 2, lane = tid & 3;
        const int* t0 = (const int*)&d_scratch[O_T0];
        const int* t1 = (const int*)&d_scratch[O_T1];
        int ya = t0[i], yb = t1[i], xa = t0[j], xb = t1[j];
        const float* rwi = &d_scratch[O_RW + (size_t)i * 448];
        const float* rwj = &d_scratch[O_RW + (size_t)j * 448];
        const int* segb = seg + (size_t)b * (HI*HI);
        float* my = &hist[j * 261 + lane * 65];
        for (int y = ya + lane; y <= yb; y += 4) {
            float ry = rwi[y];
            const int* srow = segb + (size_t)y * HI;
            for (int x = xa; x <= xb; x++) {
                float wv = ry * rwj[x];
                int s = srow[x];
                s = min(max(s, 0), NSEG - 1);
                my[s] += wv;
            }
        }
    } else {
        int t2 = tid - 128;
        if (t2 < 64) {
            float cw = d_scratch[O_CNTS + b * NSEG + t2];
            csh[t2] = (cw > 0.f) ? 1.f / cw : 0.f;
        }
        for (int t = t2; t < 64 * 48; t += 128) {
            int s = t / 48, c = t - s * 48;
            avgsh[s * 52 + c] = sums[(size_t)s * CS + c];
        }
    }
    __syncthreads();

    {
        int j = tid >> 3, sg = tid & 7;
        #pragma unroll
        for (int k = 0; k < 8; k++) {
            int s = sg * 8 + k;
            float w = hist[j * 261 + s] + hist[j * 261 + 65 + s]
                    + hist[j * 261 + 130 + s] + hist[j * 261 + 195 + s];
            hist[j * 261 + s] = w * csh[s];
        }
    }
    __syncthreads();

    int j = tid & 31;
    int csub = tid >> 5;
    const float* Wrow = &hist[j * 261];
    float* sem = &d_scratch[O_SEMRS + (size_t)b * CS * PP];
    for (int ch = 0; ch < 8; ch++) {
        if (ch > 0) {
            __syncthreads();
            for (int t = tid; t < 64 * 48; t += 256) {
                int s = t / 48, c = t - s * 48;
                avgsh[s * 52 + c] = sums[(size_t)s * CS + ch * 48 + c];
            }
            __syncthreads();
        }
        float acc[6] = {0.f, 0.f, 0.f, 0.f, 0.f, 0.f};
        for (int s = 0; s < 64; s++) {
            float w = Wrow[s];
            const float* av = &avgsh[s * 52 + csub * 6];
            #pragma unroll
            for (int k = 0; k < 6; k++) acc[k] += w * av[k];
        }
        int cbase = ch * 48 + csub * 6;
        #pragma unroll
        for (int k = 0; k < 6; k++)
            sem[(size_t)(cbase + k) * PP + i * 32 + j] = acc[k];
    }
}

// ---------------- 3x3 conv TENSOR-CORE (tf32 mma.sync m16n8k8) -------------------
// Block = 256 thr (8 warps). Warp w computes output row (r0+w), m16 out-channels,
// 4 n8 pixel fragments. K = CIN_SUB channels x 9 taps, 8-channel chunks, double buf.
// Input plane stride 360 (=8 mod 32) and weight slot stride 24 -> conflict-free LDS.
template<int CIN_TOT, int CIN_SUB, int COUT_PER, int CO_T>
__global__ void __launch_bounds__(256, 4)
conv3x3_tc(const float* __restrict__ in,
           const float* __restrict__ w0, const float* __restrict__ w1, const float* __restrict__ w2,
           float* __restrict__ o0, float* __restrict__ o1, float* __restrict__ o2,
           size_t split_stride)
{
    constexpr int CK = 8;
    constexpr int SMW = 36;
    constexpr int PLANE = 360;          // 10 * 36
    constexpr int NCH = CIN_SUB / CK;
    constexpr int WSTR = CO_T + 8;      // 24 for CO_T=16
    __shared__ unsigned int sIn[2][CK * PLANE];
    __shared__ unsigned int sW[2][CK * 9 * WSTR];

    const int tid = threadIdx.x;
    const int b = blockIdx.z;
    const int yb = blockIdx.y;
    const int split = yb >> 2;
    const int r0 = (yb & 3) * 8;
    const int co_glob = blockIdx.x * CO_T;
    const int grp = co_glob / COUT_PER;
    const int co0 = co_glob % COUT_PER;
    const float* w = (grp == 0) ? w0 : ((grp == 1) ? w1 : w2);
    float* out = ((grp == 0) ? o0 : ((grp == 1) ? o1 : o2)) + (size_t)split * split_stride;

    const int warp = tid >> 5;
    const int lane = tid & 31;
    const int gID = lane >> 2;          // 0..7
    const int ctid = lane & 3;          // 0..3
    const int lr = warp;                // output row within rowblock

    const float* inb = in + ((size_t)b * CIN_TOT + (size_t)split * CIN_SUB) * PP;

    float c0[4], c1[4], c2[4], c3[4];
    #pragma unroll
    for (int nf = 0; nf < 4; nf++) { c0[nf] = 0.f; c1[nf] = 0.f; c2[nf] = 0.f; c3[nf] = 0.f; }

    // zero both input buffers (halo + invalid rows stay zero)
    for (int t = tid; t < 2 * CK * PLANE; t += 256) (&sIn[0][0])[t] = 0u;

    auto stage = [&](int cbase, int buf) {
        unsigned int* dIn = sIn[buf];
        unsigned int* dW = sW[buf];
        // input body: CK channels x 10 rows x 8 float4
        for (int idx = tid; idx < CK * 80; idx += 256) {
            int k = idx / 80;
            int rem = idx - k * 80;
            int r = rem >> 3;
            int v = rem & 7;
            int iy = r0 - 1 + r;
            if (iy >= 0 && iy < 32) {
                float4 val = *(const float4*)&inb[(size_t)(cbase + k) * PP + iy * 32 + v * 4];
                unsigned int* d = &dIn[k * PLANE + r * SMW + 1 + v * 4];
                d[0] = to_tf32(val.x); d[1] = to_tf32(val.y);
                d[2] = to_tf32(val.z); d[3] = to_tf32(val.w);
            }
        }
        // weights: CO_T x CK x 9 -> sW[(t*8+k)*WSTR + co]
        for (int idx = tid; idx < CO_T * CK * 9; idx += 256) {
            int co = idx / (CK * 9);
            int rem = idx - co * (CK * 9);
            int k = rem / 9;
            int t = rem - k * 9;
            float wv = w[((size_t)(co0 + co) * CIN_TOT + split * CIN_SUB + cbase + k) * 9 + t];
            dW[(t * 8 + k) * WSTR + co] = to_tf32(wv);
        }
    };

    __syncthreads();
    stage(0, 0);
    __syncthreads();
    for (int cc = 0; cc < NCH; cc++) {
        int buf = cc & 1;
        if (cc + 1 < NCH) stage((cc + 1) * CK, buf ^ 1);
        #pragma unroll
        for (int t = 0; t < 9; t++) {
            const int ky = t / 3, kx = t - 3 * (t / 3);
            const unsigned int* wp = &sW[buf][t * 8 * WSTR];
            unsigned int a0 = wp[ctid * WSTR + gID];
            unsigned int a1 = wp[ctid * WSTR + gID + 8];
            unsigned int a2 = wp[(ctid + 4) * WSTR + gID];
            unsigned int a3 = wp[(ctid + 4) * WSTR + gID + 8];
            const unsigned int* ip = &sIn[buf][(lr + ky) * SMW + kx];
            #pragma unroll
            for (int nf = 0; nf < 4; nf++) {
                unsigned int b0 = ip[ctid * PLANE + nf * 8 + gID];
                unsigned int b1 = ip[(ctid + 4) * PLANE + nf * 8 + gID];
                asm volatile(
                    "mma.sync.aligned.m16n8k8.row.col.f32.tf32.tf32.f32 "
                    "{%0,%1,%2,%3}, {%4,%5,%6,%7}, {%8,%9}, {%0,%1,%2,%3};"
                    : "+f"(c0[nf]), "+f"(c1[nf]), "+f"(c2[nf]), "+f"(c3[nf])
                    : "r"(a0), "r"(a1), "r"(a2), "r"(a3), "r"(b0), "r"(b1));
            }
        }
        __syncthreads();
    }

    // write out: rows co0+gID and co0+gID+8; cols nf*8 + 2*ctid (+1)
    size_t rowbase0 = ((size_t)b * COUT_PER + co0 + gID) * PP + (size_t)(r0 + lr) * 32;
    size_t rowbase1 = rowbase0 + (size_t)8 * PP;
    #pragma unroll
    for (int nf = 0; nf < 4; nf++) {
        int col = nf * 8 + 2 * ctid;
        *(float2*)&out[rowbase0 + col] = make_float2(c0[nf], c1[nf]);
        *(float2*)&out[rowbase1 + col] = make_float2(c2[nf], c3[nf]);
    }
}

// ---------------- 3x3 conv v2 scalar (R14-proven) for the small convs ------------
template<int CIN_TOT, int CIN_SUB, int COUT_PER, int CO_T, int TH_CO, int MINB>
__global__ void __launch_bounds__((CO_T / TH_CO) * 32, MINB)
conv3x3_v2(const float* __restrict__ in,
           const float* __restrict__ w0, const float* __restrict__ w1, const float* __restrict__ w2,
           float* __restrict__ o0, float* __restrict__ o1, float* __restrict__ o2,
           size_t split_stride)
{
    constexpr int CK = 4;
    constexpr int ROWS = 8;
    constexpr int NT = (CO_T / TH_CO) * 32;
    constexpr int SMW = 35;
    constexpr int PLANE = (ROWS + 2) * SMW;
    constexpr int NCH = CIN_SUB / CK;
    __shared__ float sIn[2][CK * PLANE];
    __shared__ float sW[2][CK * CO_T * 9];

    const int tid = threadIdx.x;
    const int b = blockIdx.z;
    const int yb = blockIdx.y;
    const int split = yb >> 2;
    const int r0 = (yb & 3) * ROWS;
    const int co_glob = blockIdx.x * CO_T;
    const int grp = co_glob / COUT_PER;
    const int co0 = co_glob % COUT_PER;
    const float* w = (grp == 0) ? w0 : ((grp == 1) ? w1 : w2);
    float* out = ((grp == 0) ? o0 : ((grp == 1) ? o1 : o2)) + (size_t)split * split_stride;

    const int pg = tid & 31;
    const int cg = tid >> 5;
    const int lr = (pg * 8) >> 5;
    const int col0 = (pg * 8) & 31;
    const int gy = r0 + lr;

    const float* inb = in + ((size_t)b * CIN_TOT + (size_t)split * CIN_SUB) * PP;

    float acc[TH_CO * 8];
    #pragma unroll
    for (int t = 0; t < TH_CO * 8; t++) acc[t] = 0.f;

    for (int t = tid; t < 2 * CK * PLANE; t += NT) (&sIn[0][0])[t] = 0.f;

    auto stage = [&](int c0, int buf) {
        float* dIn = sIn[buf];
        float* dW = sW[buf];
        for (int idx = tid; idx < CK * 80; idx += NT) {
            int k = idx / 80;
            int rem = idx - k * 80;
            int r = rem >> 3;
            int v = rem & 7;
            int iy = r0 - 1 + r;
            if (iy >= 0 && iy < 32) {
                float4 val = *(const float4*)&inb[(size_t)(c0 + k) * PP + iy * 32 + v * 4];
                float* d = &dIn[k * PLANE + r * SMW + 1 + v * 4];
                d[0] = val.x; d[1] = val.y; d[2] = val.z; d[3] = val.w;
            }
        }
        for (int idx = tid; idx < CK * CO_T * 9; idx += NT) {
            int k = idx / (CO_T * 9);
            int rem = idx - k * (CO_T * 9);
            int co = rem / 9;
            int t = rem - co * 9;
            dW[idx] = w[((size_t)(co0 + co) * CIN_TOT + split * CIN_SUB + c0 + k) * 9 + t];
        }
    };

    __syncthreads();
    stage(0, 0);
    __syncthreads();
    for (int cc = 0; cc < NCH; cc++) {
        int buf = cc & 1;
        if (cc + 1 < NCH) stage((cc + 1) * CK, buf ^ 1);
        #pragma unroll
        for (int k = 0; k < CK; k++) {
            const float* pl = &sIn[buf][k * PLANE + lr * SMW + col0];
            const float* wk = &sW[buf][k * CO_T * 9 + cg * TH_CO * 9];
            #pragma unroll
            for (int ky = 0; ky < 3; ky++) {
                float win[10];
                #pragma unroll
                for (int t = 0; t < 10; t++) win[t] = pl[ky * SMW + t];
                #pragma unroll
                for (int co = 0; co < TH_CO; co++) {
                    float wa = wk[co * 9 + ky * 3 + 0];
                    float wb = wk[co * 9 + ky * 3 + 1];
                    float wc = wk[co * 9 + ky * 3 + 2];
                    #pragma unroll
                    for (int px = 0; px < 8; px++)
                        acc[co * 8 + px] += win[px] * wa + win[px + 1] * wb + win[px + 2] * wc;
                }
            }
        }
        __syncthreads();
    }
    #pragma unroll
    for (int co = 0; co < TH_CO; co++) {
        int oc = co0 + cg * TH_CO + co;
        #pragma unroll
        for (int px = 0; px < 8; px++)
            out[((size_t)b * COUT_PER + oc) * PP + gy * 32 + col0 + px] = acc[co * 8 + px];
    }
}

// ---------------- hsh epilogue: relu(sum of 2 splits + bias) ----------------
__global__ void k_hsh_epi(const float* __restrict__ b0, const float* __restrict__ b1,
                          const float* __restrict__ b2) {
    int idx = blockIdx.x * 256 + threadIdx.x;
    if (idx >= (int)SZ_HSH3) return;
    int g = idx / (int)SZ_HSH1;
    int ch = (idx >> 10) % HM;
    const float* bp = (g == 0) ? b0 : ((g == 1) ? b1 : b2);
    float v = d_scratch[O_HSHS + idx] + d_scratch[O_HSHS + SZ_HSH3 + idx] + bp[ch];
    d_scratch[O_HSH + idx] = fmaxf(v, 0.f);
}

// ---------------- layernorm stats ----------------
__global__ void k_ln_big(const float* __restrict__ x) {
    int b = blockIdx.y;
    const float* xb = x + (size_t)b * CM * PP;
    const int chunk = CM * PP / 64;
    int start = blockIdx.x * chunk;
    float s = 0.f, q = 0.f;
    #pragma unroll 4
    for (int i = threadIdx.x; i < chunk; i += 256) {
        float v = xb[start + i];
        s += v; q += v * v;
    }
    __shared__ float ss[256], sq[256];
    int t = threadIdx.x;
    ss[t] = s; sq[t] = q;
    __syncthreads();
    for (int o = 128; o > 0; o >>= 1) {
        if (t < o) { ss[t] += ss[t + o]; sq[t] += sq[t + o]; }
        __syncthreads();
    }
    if (t == 0) {
        atomicAdd(&d_scratch[O_LNACC + b * 2 + 0], ss[0]);
        atomicAdd(&d_scratch[O_LNACC + b * 2 + 1], sq[0]);
    }
}

__global__ void k_ln_fin() {
    int b = threadIdx.x;
    if (b >= BB) return;
    float N = (float)(CM * PP);
    float mu = d_scratch[O_LNACC + b * 2] / N;
    float var = d_scratch[O_LNACC + b * 2 + 1] / N - mu * mu;
    d_scratch[O_LNST + b * 2] = mu;
    d_scratch[O_LNST + b * 2 + 1] = rsqrtf(fmaxf(var, 0.f) + 1e-12f);
}

__global__ void k_ln_small(size_t off_in, int n, size_t off_stat) {
    int b = blockIdx.x;
    const float* p = &d_scratch[off_in + (size_t)b * n];
    float s = 0.f, q = 0.f;
    for (int i = threadIdx.x; i < n; i += 256) {
        float v = p[i]; s += v; q += v * v;
    }
    __shared__ float ss[256], sq[256];
    int t = threadIdx.x;
    ss[t] = s; sq[t] = q;
    __syncthreads();
    for (int o = 128; o > 0; o >>= 1) {
        if (t < o) { ss[t] += ss[t + o]; sq[t] += sq[t + o]; }
        __syncthreads();
    }
    if (t == 0) {
        float N = (float)n;
        float mu = ss[0] / N;
        float var = sq[0] / N - mu * mu;
        d_scratch[off_stat + b * 2] = mu;
        d_scratch[off_stat + b * 2 + 1] = rsqrtf(fmaxf(var, 0.f) + 1e-12f);
    }
}

// ---------------- pre-contract w_be0 with wc0 ----------------
__global__ void k_weff(const float* __restrict__ w_be0, const float* __restrict__ b_be0,
                       const float* __restrict__ wc0) {
    __shared__ float sw[8 * 384];
    int tid = threadIdx.x;
    int mtb = blockIdx.x;
    int cch = blockIdx.y;
    int c0 = cch * 384;
    for (int idx = tid; idx < 8 * 384; idx += 128) {
        int o = idx / 384;
        int cl = idx - o * 384;
        sw[idx] = wc0[(size_t)o * CM + c0 + cl];
    }
    __syncthreads();
    int mt = mtb * 128 + tid;
    float acc[8];
    #pragma unroll
    for (int o = 0; o < 8; o++) acc[o] = 0.f;
    for (int cl = 0; cl < 384; cl++) {
        float wv = w_be0[(size_t)(c0 + cl) * (HM * 9) + mt];
        #pragma unroll
        for (int o = 0; o < 8; o++) acc[o] += sw[o * 384 + cl] * wv;
    }
    #pragma unroll
    for (int o = 0; o < 8; o++)
        atomicAdd(&d_scratch[O_WEFF + (size_t)o * (HM * 9) + mt], acc[o]);
    if (mtb == 0 && tid < 8) {
        int o = tid;
        float bc = 0.f, s0 = 0.f;
        for (int cl = 0; cl < 384; cl++) {
            float wcv = sw[o * 384 + cl];
            bc += wcv * b_be0[c0 + cl];
            s0 += wcv;
        }
        atomicAdd(&d_scratch[O_BCONST + o], bc);
        atomicAdd(&d_scratch[O_S0 + o], s0);
    }
}

// ---------------- combine0: G = wc0.(xn*gamma), A = wc0.x ----------------
__global__ void k_combine0(const float* __restrict__ x, const float* __restrict__ wc0,
                           const float* __restrict__ bg0) {
    __shared__ float sw[8 * 24];
    __shared__ float sb[24];
    int tid = threadIdx.x;
    int b = blockIdx.z;
    int cc = blockIdx.y;               // 0..63, 24 channels each
    int p = blockIdx.x * 256 + tid;
    if (tid < 8 * 24) {
        int o = tid / 24;
        int c = tid - o * 24;
        sw[tid] = wc0[(size_t)o * CM + cc * 24 + c];
    }
    if (tid >= 224 && tid < 248) sb[tid - 224] = bg0[cc * 24 + (tid - 224)];
    __syncthreads();
    float mu = d_scratch[O_LNST + b * 2];
    float rs = d_scratch[O_LNST + b * 2 + 1];
    float accG[8], accA[8];
    #pragma unroll
    for (int o = 0; o < 8; o++) { accG[o] = 0.f; accA[o] = 0.f; }
    size_t base = ((size_t)b * CM + (size_t)cc * 24) * PP + p;
    const float* g0 = &d_scratch[O_G0S];
    #pragma unroll 4
    for (int c = 0; c < 24; c++) {
        size_t a = base + (size_t)c * PP;
        float xv = x[a];
        float gv = g0[a] + sb[c];
        float val = (xv - mu) * rs * gv;
        #pragma unroll
        for (int o = 0; o < 8; o++) {
            float wv = sw[o * 24 + c];
            accG[o] += wv * val;
            accA[o] += wv * xv;
        }
    }
    #pragma unroll
    for (int o = 0; o < 8; o++) {
        atomicAdd(&d_scratch[O_H1PRE + ((size_t)b * 8 + o) * PP + p], accG[o]);
        atomicAdd(&d_scratch[O_A     + ((size_t)b * 8 + o) * PP + p], accA[o]);
    }
}

// ---------------- assemble h1 (sums 4 beta-conv splits) ----------------
__global__ void k_bias_sp0(const float* __restrict__ bias0) {
    int idx = blockIdx.x * blockDim.x + threadIdx.x;
    if (idx >= (int)SZ_SMALL) return;
    int b = idx >> 13;
    int o = (idx >> 10) & 7;
    float mu = d_scratch[O_LNST + b * 2];
    float rs = d_scratch[O_LNST + b * 2 + 1];
    float bc = d_scratch[O_BCS + idx] + d_scratch[O_BCS + SZ_SMALL + idx]
             + d_scratch[O_BCS + 2*SZ_SMALL + idx] + d_scratch[O_BCS + 3*SZ_SMALL + idx];
    float v = d_scratch[O_H1PRE + idx]
            + (d_scratch[O_A + idx] - mu * d_scratch[O_S0 + o]) * rs
            + bc
            + d_scratch[O_BCONST + o]
            + bias0[o];
    d_scratch[O_H1 + idx] = softplusf(v);
}

// ---------------- spade1 combine + 1x1 (8->16) + softplus ----------------
__global__ void __launch_bounds__(128) k_combine1(const float* __restrict__ wc1,
                           const float* __restrict__ bias1,
                           const float* __restrict__ bg1, const float* __restrict__ bbe1) {
    int b = blockIdx.y;
    int p = blockIdx.x * 128 + threadIdx.x;
    float mu = d_scratch[O_LN1 + b * 2];
    float rs = d_scratch[O_LN1 + b * 2 + 1];
    float val[8];
    #pragma unroll
    for (int c = 0; c < 8; c++) {
        size_t a = ((size_t)b * 8 + c) * PP + p;
        float gv = d_scratch[O_G1S + a] + d_scratch[O_G1S + SZ_SMALL + a]
                 + d_scratch[O_G1S + 2*SZ_SMALL + a] + d_scratch[O_G1S + 3*SZ_SMALL + a]
                 + bg1[c];
        float bv = d_scratch[O_BE1S + a] + d_scratch[O_BE1S + SZ_SMALL + a]
                 + d_scratch[O_BE1S + 2*SZ_SMALL + a] + d_scratch[O_BE1S + 3*SZ_SMALL + a]
                 + bbe1[c];
        float hv = d_scratch[O_H1 + a];
        val[c] = (hv - mu) * rs * (1.f + gv) + bv;
    }
    #pragma unroll
    for (int o = 0; o < 16; o++) {
        float a = bias1[o];
        #pragma unroll
        for (int c = 0; c < 8; c++) a += wc1[o * 8 + c] * val[c];
        d_scratch[O_H2 + ((size_t)b * 16 + o) * PP + p] = softplusf(a);
    }
}

// ---------------- spade2 combine + 1x1 (16->1) + softplus -> output ------------
__global__ void __launch_bounds__(128) k_combine2(const float* __restrict__ wc2,
                           const float* __restrict__ bias2,
                           const float* __restrict__ bg2, const float* __restrict__ bbe2,
                           float* __restrict__ out) {
    int b = blockIdx.y;
    int p = blockIdx.x * 128 + threadIdx.x;
    float mu = d_scratch[O_LN2 + b * 2];
    float rs = d_scratch[O_LN2 + b * 2 + 1];
    float a = bias2[0];
    #pragma unroll
    for (int c = 0; c < 16; c++) {
        size_t idx = ((size_t)b * 16 + c) * PP + p;
        float hv = d_scratch[O_H2 + idx];
        float gv = d_scratch[O_G2S + idx] + d_scratch[O_G2S + SZ_MED + idx]
                 + d_scratch[O_G2S + 2*SZ_MED + idx] + d_scratch[O_G2S + 3*SZ_MED + idx]
                 + bg2[c];
        float bv = d_scratch[O_BE2S + idx] + d_scratch[O_BE2S + SZ_MED + idx]
                 + d_scratch[O_BE2S + 2*SZ_MED + idx] + d_scratch[O_BE2S + 3*SZ_MED + idx]
                 + bbe2[c];
        float val = (hv - mu) * rs * (1.f + gv) + bv;
        a += wc2[c] * val;
    }
    out[(size_t)b * PP + p] = softplusf(a);
}

// ---------------- launch ----------------
extern "C" void kernel_launch(void* const* d_in, const int* in_sizes, int n_in,
                              void* d_out, int out_size) {
    const float* x_main = (const float*)d_in[0];
    const float* f_sem  = (const float*)d_in[1];
    const float* w_sh0  = (const float*)d_in[2];
    const float* b_sh0  = (const float*)d_in[3];
    const float* w_g0   = (const float*)d_in[4];
    const float* b_g0   = (const float*)d_in[5];
    const float* w_be0  = (const float*)d_in[6];
    const float* b_be0  = (const float*)d_in[7];
    const float* w_sh1  = (const float*)d_in[8];
    const float* b_sh1  = (const float*)d_in[9];
    const float* w_g1   = (const float*)d_in[10];
    const float* b_g1   = (const float*)d_in[11];
    const float* w_be1  = (const float*)d_in[12];
    const float* b_be1  = (const float*)d_in[13];
    const float* w_sh2  = (const float*)d_in[14];
    const float* b_sh2  = (const float*)d_in[15];
    const float* w_g2   = (const float*)d_in[16];
    const float* b_g2   = (const float*)d_in[17];
    const float* w_be2  = (const float*)d_in[18];
    const float* b_be2  = (const float*)d_in[19];
    const float* w_c0   = (const float*)d_in[20];
    const float* bias0  = (const float*)d_in[21];
    const float* w_c1   = (const float*)d_in[22];
    const float* bias1  = (const float*)d_in[23];
    const float* w_c2   = (const float*)d_in[24];
    const float* bias2  = (const float*)d_in[25];
    const int*   segmap = (const int*)d_in[26];

    float* S = nullptr;
    cudaGetSymbolAddress((void**)&S, d_scratch);
    float* semrs = S + O_SEMRS;
    float* hsh0 = S + O_HSH;
    float* hsh1 = S + O_HSH + SZ_HSH1;
    float* hsh2 = S + O_HSH + 2 * SZ_HSH1;
    float* hshS0 = S + O_HSHS;
    float* hshS1 = S + O_HSHS + SZ_HSH1;
    float* hshS2 = S + O_HSHS + 2 * SZ_HSH1;
    float* g0s = S + O_G0S;
    float* g1s  = S + O_G1S;
    float* be1s = S + O_BE1S;
    float* g2s  = S + O_G2S;
    float* be2s = S + O_BE2S;
    float* bcs  = S + O_BCS;
    float* weff = S + O_WEFF;

    // 0
    k_zero<<<129, 256>>>();
    // 1: coalesced segment sums
    k_seg_acc<<<BB * 48, 256>>>(f_sem, segmap);
    // 2: fused wseg + avg-fold + sem_rs
    k_semrs_fused<<<dim3(32, BB), 256>>>(segmap);
    // 3: shared convs TENSOR (3 groups, CIN split 2)  << ncu slot >>
    conv3x3_tc<CS, CS/NSPLIT_SH, HM, 16><<<dim3(3 * HM / 16, 4 * NSPLIT_SH, BB), 256>>>(
        semrs, w_sh0, w_sh1, w_sh2, hshS0, hshS1, hshS2, SZ_HSH3);
    // 4: epilogue -> hsh
    k_hsh_epi<<<(int)(SZ_HSH3 / 256), 256>>>(b_sh0, b_sh1, b_sh2);
    // 5: gamma conv TENSOR: 128->1536, no split
    conv3x3_tc<HM, HM, CM, 16><<<dim3(CM / 16, 4, BB), 256>>>(
        hsh0, w_g0, w_g0, w_g0, g0s, g0s, g0s, SZ_G0);
    // 6,7
    k_ln_big<<<dim3(64, BB), 256>>>(x_main);
    k_ln_fin<<<1, 32>>>();
    // 8: beta-path weight pre-contraction
    k_weff<<<dim3(9, 4), 128>>>(w_be0, b_be0, w_c0);
    // 9: beta-path conv 128 -> 8, split 4 (scalar)
    conv3x3_v2<HM, HM/NSPLIT_SM, 8, 8, 2, 8><<<dim3(1, 4 * NSPLIT_SM, BB), 128>>>(
        hsh0, weff, weff, weff, bcs, bcs, bcs, SZ_SMALL);
    // 10: combine0 (G and A partial sums), 512 blocks
    k_combine0<<<dim3(4, 64, BB), 256>>>(x_main, w_c0, b_g0);
    // 11
    k_bias_sp0<<<(int)(SZ_SMALL / 256), 256>>>(bias0);
    // 12
    k_ln_small<<<BB, 256>>>(O_H1, 8 * PP, O_LN1);
    // 13: spade1 gamma+beta convs: 128 -> 8 (x2 groups), split 4 (scalar)
    conv3x3_v2<HM, HM/NSPLIT_SM, 8, 8, 2, 8><<<dim3(2, 4 * NSPLIT_SM, BB), 128>>>(
        hsh1, w_g1, w_be1, w_be1, g1s, be1s, be1s, SZ_SMALL);
    // 14
    k_combine1<<<dim3(8, BB), 128>>>(w_c1, bias1, b_g1, b_be1);
    // 15
    k_ln_small<<<BB, 256>>>(O_H2, 16 * PP, O_LN2);
    // 16: spade2 gamma+beta convs: 128 -> 16 (x2 groups), split 4 (scalar)
    conv3x3_v2<HM, HM/NSPLIT_SM, 16, 8, 2, 8><<<dim3(4, 4 * NSPLIT_SM, BB), 128>>>(
        hsh2, w_g2, w_be2, w_be2, g2s, be2s, be2s, SZ_MED);
    // 17
    k_combine2<<<dim3(8, BB), 128>>>(w_c2, bias2, b_g2, b_be2, (float*)d_out);
}